// round 1
// baseline (speedup 1.0000x reference)
#include <cuda_runtime.h>
#include <cstdint>

// Problem constants
#define Bn 64
#define Tn 1024
#define Hn 512
#define In 64
#define On 8
#define ALPHAc 0.2f
#define NSTDc 0.05f

// Decomposition
#define CL 8                 // CTAs per cluster (column slices of H)
#define BPC 4                // batches per cluster
#define NCL (Bn / BPC)       // 16 clusters
#define GRIDn (NCL * CL)     // 128 CTAs
#define JC (Hn / CL)         // 64 columns per CTA
#define KRAW (Hn + In + 1)   // 577 (wrec rows + wi rows + bias row)
#define KP 592               // padded to /4 for k-slicing and /4 unroll
#define NT 256
#define KSL (KP / 4)         // 148 k's per slice

// Shared memory layout (in floats)
#define SM_WC   0                       // Wc[KP][JC]       = 37888
#define SM_WO   (KP * JC)               // Wo[Hn][On]       = 4096
#define SM_R4   (SM_WO + Hn * On)       // r4[KP][4]        = 2368
#define SM_RED  (SM_R4 + KP * 4)        // red              = 1024
#define SM_TOT  (SM_RED + 1024)         // 45376 floats = 181504 bytes

extern __shared__ float smem[];

__global__ void __cluster_dims__(CL, 1, 1) __launch_bounds__(NT, 1)
rnn_kernel(const float* __restrict__ input, const float* __restrict__ noise,
           const float* __restrict__ wi,    const float* __restrict__ si,
           const float* __restrict__ wrec,  const float* __restrict__ bvec,
           const float* __restrict__ wo,    const float* __restrict__ so,
           const float* __restrict__ wim,   const float* __restrict__ wrm,
           const float* __restrict__ wom,   const float* __restrict__ h0,
           float* __restrict__ outp, float* __restrict__ traj)
{
    float* Wc  = smem + SM_WC;
    float* Wos = smem + SM_WO;
    float* r4  = smem + SM_R4;
    float* red = smem + SM_RED;

    const int tid = threadIdx.x;
    const int cta = blockIdx.x;
    const int rk  = cta % CL;       // rank within cluster -> column slice
    const int cl  = cta / CL;       // cluster id -> batch group
    const int b0  = cl * BPC;
    const int j0  = rk * JC;

    // ---- init: effective weights into smem (done once) ----
    for (int idx = tid; idx < Hn * JC; idx += NT) {
        int k = idx / JC, j = idx % JC;
        size_t g = (size_t)k * Hn + j0 + j;
        Wc[k * JC + j] = fabsf(wrec[g]) * wrm[g];
    }
    for (int idx = tid; idx < In * JC; idx += NT) {
        int i = idx / JC, j = idx % JC;
        size_t g = (size_t)i * Hn + j0 + j;
        Wc[(Hn + i) * JC + j] = wi[g] * si[i] * wim[g];
    }
    for (int idx = tid; idx < JC; idx += NT)
        Wc[(Hn + In) * JC + idx] = bvec[j0 + idx];
    for (int idx = tid; idx < (KP - KRAW) * JC; idx += NT)
        Wc[KRAW * JC + idx] = 0.f;
    for (int idx = tid; idx < Hn * On; idx += NT)
        Wos[idx] = wo[idx] * so[idx % On] * wom[idx];
    // constant rows of r4: bias row = 1, pad rows = 0 (never rewritten)
    for (int idx = tid; idx < (KP - Hn - In) * 4; idx += NT) {
        int row = Hn + In + idx / 4;
        r4[row * 4 + (idx % 4)] = (row == Hn + In) ? 1.0f : 0.0f;
    }
    // zero this cluster's slice of the `out` region (atomics accumulate later)
    {
        const int per = BPC * Tn * On / CL;  // 4096 floats per CTA
        for (int idx = tid; idx < per; idx += NT) {
            int g = rk * per + idx;
            int bb = g / (Tn * On);
            int rest = g % (Tn * On);
            outp[(size_t)(b0 + bb) * Tn * On + rest] = 0.f;
        }
    }

    // ---- per-thread persistent state: h for (batch ub, column jg) ----
    const int ub = tid >> 6;     // 0..3
    const int uj = tid & 63;
    const int jg = j0 + uj;
    float h = h0[jg];
    traj[(size_t)(b0 + ub) * (Tn + 1) * Hn + jg] = h;   // t = 0 row

    __syncthreads();

    const int ks   = tid >> 6;         // k-slice role (same id as ub)
    const int kbeg = ks * KSL;

    for (int t = 0; t <= Tn; t++) {
        // cluster barrier: release h stores of step t-1, acquire peers'
        asm volatile("barrier.cluster.arrive.aligned;" ::: "memory");
        asm volatile("barrier.cluster.wait.aligned;"   ::: "memory");

        // prefetch this step's noise early (consumed ~2.5k cycles later)
        float nval = 0.f;
        if (t < Tn)
            nval = noise[(size_t)(b0 + ub) * Tn * Hn + (size_t)t * Hn + jg];

        // load relu(h_t) for all 4 batches into r4[k][0..3]
        {
            const float* tb = traj + (size_t)b0 * (Tn + 1) * Hn + (size_t)t * Hn;
            const size_t bs = (size_t)(Tn + 1) * Hn;
            #pragma unroll
            for (int rep = 0; rep < 2; rep++) {
                int k = tid + rep * NT;
                float4 v;
                v.x = fmaxf(tb[k],          0.f);
                v.y = fmaxf(tb[bs + k],     0.f);
                v.z = fmaxf(tb[2 * bs + k], 0.f);
                v.w = fmaxf(tb[3 * bs + k], 0.f);
                *(float4*)(r4 + k * 4) = v;
            }
            // x_t rows (k = 512..575), no relu
            if (t < Tn && tid < In) {
                const float* xb = input + (size_t)b0 * Tn * In + (size_t)t * In + tid;
                const size_t xs = (size_t)Tn * In;
                float4 v;
                v.x = xb[0];
                v.y = xb[xs];
                v.z = xb[2 * xs];
                v.w = xb[3 * xs];
                *(float4*)(r4 + (Hn + tid) * 4) = v;
            }
        }
        __syncthreads();

        // out[t-1] = relu(h_t) @ Wo_eff  — this rank covers k in [j0, j0+64)
        if (t > 0) {
            int q = tid & 31, koff = tid >> 5;
            int ob = q >> 3, oo = q & 7;
            float acc = 0.f;
            int kb = j0 + koff * 8;
            #pragma unroll
            for (int u = 0; u < 8; u++) {
                int k = kb + u;
                acc += r4[k * 4 + ob] * Wos[k * On + oo];
            }
            red[koff * 32 + q] = acc;
            __syncthreads();
            if (tid < 32) {
                float s = 0.f;
                #pragma unroll
                for (int w = 0; w < 8; w++) s += red[w * 32 + tid];
                atomicAdd(&outp[(size_t)(b0 + (tid >> 3)) * Tn * On
                                + (size_t)(t - 1) * On + (tid & 7)], s);
            }
            __syncthreads();
        }
        if (t == Tn) break;

        // GEMM slice: y[b][uj] partial over k in [kbeg, kbeg+148)
        float a0 = 0.f, a1 = 0.f, a2 = 0.f, a3 = 0.f;
        #pragma unroll 4
        for (int k = kbeg; k < kbeg + KSL; k++) {
            float4 rv = *(const float4*)(r4 + k * 4);   // broadcast
            float  w  = Wc[k * JC + uj];
            a0 = fmaf(rv.x, w, a0);
            a1 = fmaf(rv.y, w, a1);
            a2 = fmaf(rv.z, w, a2);
            a3 = fmaf(rv.w, w, a3);
        }
        red[(ks * 4 + 0) * JC + uj] = a0;
        red[(ks * 4 + 1) * JC + uj] = a1;
        red[(ks * 4 + 2) * JC + uj] = a2;
        red[(ks * 4 + 3) * JC + uj] = a3;
        __syncthreads();

        float y = red[(0 * 4 + ub) * JC + uj] + red[(1 * 4 + ub) * JC + uj]
                + red[(2 * 4 + ub) * JC + uj] + red[(3 * 4 + ub) * JC + uj];
        h = (1.f - ALPHAc) * h + NSTDc * nval + ALPHAc * y;
        traj[(size_t)(b0 + ub) * (Tn + 1) * Hn + (size_t)(t + 1) * Hn + jg] = h;
        // no trailing syncthreads needed: next cluster barrier is a full barrier
    }
}

extern "C" void kernel_launch(void* const* d_in, const int* in_sizes, int n_in,
                              void* d_out, int out_size)
{
    const float* input = (const float*)d_in[0];
    const float* noise = (const float*)d_in[1];
    const float* wi    = (const float*)d_in[2];
    const float* si    = (const float*)d_in[3];
    const float* wrec  = (const float*)d_in[4];
    const float* bvec  = (const float*)d_in[5];
    const float* wo    = (const float*)d_in[6];
    const float* so    = (const float*)d_in[7];
    const float* wim   = (const float*)d_in[8];
    const float* wrm   = (const float*)d_in[9];
    const float* wom   = (const float*)d_in[10];
    const float* h0    = (const float*)d_in[11];

    float* outp = (float*)d_out;                      // [B, T, O]
    float* traj = (float*)d_out + (size_t)Bn * Tn * On;  // [B, T+1, H]

    const int smem_bytes = SM_TOT * sizeof(float);    // 181504
    cudaFuncSetAttribute(rnn_kernel,
                         cudaFuncAttributeMaxDynamicSharedMemorySize, smem_bytes);

    rnn_kernel<<<GRIDn, NT, smem_bytes>>>(input, noise, wi, si, wrec, bvec,
                                          wo, so, wim, wrm, wom, h0,
                                          outp, traj);
}

// round 2
// speedup vs baseline: 1.0250x; 1.0250x over previous
#include <cuda_runtime.h>
#include <cooperative_groups.h>
#include <cstdint>

namespace cg = cooperative_groups;

// Problem constants
#define Bn 64
#define Tn 1024
#define Hn 512
#define In 64
#define On 8
#define ALPHAc 0.2f
#define NSTDc 0.05f

// Decomposition
#define CL 8                 // CTAs per cluster (column slices of H)
#define BPC 4                // batches per cluster
#define NCL (Bn / BPC)       // 16 clusters
#define GRIDn (NCL * CL)     // 128 CTAs
#define JC (Hn / CL)         // 64 columns per CTA
#define KRAW (Hn + In + 1)   // 577
#define KP 608               // padded: /8 slices, /4 unroll  (KSL = 76)
#define NT 512
#define NSL 8
#define KSL (KP / NSL)       // 76

// Shared memory layout (floats)
#define SM_WC   0                         // Wc[KP][JC]      38912
#define SM_WO   (SM_WC + KP * JC)         // Wo[Hn][On]       4096
#define SM_R4   (SM_WO + Hn * On)         // r4[2][KP][4]     4864
#define SM_STG  (SM_R4 + 2 * KP * 4)      // staging[256]      256
#define SM_RED  (SM_STG + 256)            // red[8][4][64]    2048
#define SM_RED2 (SM_RED + 2048)           // red2[16][32]      512
#define SM_TOT  (SM_RED2 + 512)           // 50688 f = 202752 B

extern __shared__ float smem[];

__global__ void __cluster_dims__(CL, 1, 1) __launch_bounds__(NT, 1)
rnn_kernel(const float* __restrict__ input, const float* __restrict__ noise,
           const float* __restrict__ wi,    const float* __restrict__ si,
           const float* __restrict__ wrec,  const float* __restrict__ bvec,
           const float* __restrict__ wo,    const float* __restrict__ so,
           const float* __restrict__ wim,   const float* __restrict__ wrm,
           const float* __restrict__ wom,   const float* __restrict__ h0,
           float* __restrict__ outp, float* __restrict__ traj)
{
    cg::cluster_group cluster = cg::this_cluster();

    float* Wc  = smem + SM_WC;
    float* Wos = smem + SM_WO;
    float* r4  = smem + SM_R4;     // two parity buffers of KP*4
    float* stg = smem + SM_STG;
    float* red = smem + SM_RED;
    float* red2= smem + SM_RED2;

    const int tid = threadIdx.x;
    const int cta = blockIdx.x;
    const int rk  = cta % CL;
    const int cl  = cta / CL;
    const int b0  = cl * BPC;
    const int j0  = rk * JC;

    // ---- init: effective weights ----
    for (int idx = tid; idx < Hn * JC; idx += NT) {
        int k = idx / JC, j = idx % JC;
        size_t g = (size_t)k * Hn + j0 + j;
        Wc[k * JC + j] = fabsf(wrec[g]) * wrm[g];
    }
    for (int idx = tid; idx < In * JC; idx += NT) {
        int i = idx / JC, j = idx % JC;
        size_t g = (size_t)i * Hn + j0 + j;
        Wc[(Hn + i) * JC + j] = wi[g] * si[i] * wim[g];
    }
    for (int idx = tid; idx < JC; idx += NT)
        Wc[(Hn + In) * JC + idx] = bvec[j0 + idx];
    for (int idx = tid; idx < (KP - KRAW) * JC; idx += NT)
        Wc[KRAW * JC + idx] = 0.f;
    for (int idx = tid; idx < Hn * On; idx += NT)
        Wos[idx] = wo[idx] * so[idx % On] * wom[idx];

    // constant rows of both r4 parity buffers: bias row = 1, pads = 0
    for (int p = 0; p < 2; p++)
        for (int idx = tid; idx < (KP - Hn - In) * 4; idx += NT) {
            int row = Hn + In + idx / 4;
            r4[p * KP * 4 + row * 4 + (idx % 4)] = (row == Hn + In) ? 1.0f : 0.0f;
        }

    // buffer 0: relu(h0) rows (same for all 4 batches)
    for (int k = tid; k < Hn; k += NT) {
        float f = fmaxf(h0[k], 0.f);
        *(float4*)(r4 + k * 4) = make_float4(f, f, f, f);
    }
    // buffer 0: x(0) rows
    if (tid < In) {
        const float* xb = input + (size_t)b0 * Tn * In + tid;
        const size_t xs = (size_t)Tn * In;
        *(float4*)(r4 + (Hn + tid) * 4) =
            make_float4(xb[0], xb[xs], xb[2 * xs], xb[3 * xs]);
    }
    // zero this cluster's slice of out (atomics accumulate later)
    {
        const int per = BPC * Tn * On / CL;  // 4096 floats per CTA
        for (int idx = tid; idx < per; idx += NT) {
            int g = rk * per + idx;
            int bb = g / (Tn * On);
            int rest = g % (Tn * On);
            outp[(size_t)(b0 + bb) * Tn * On + rest] = 0.f;
        }
    }

    // persistent h state: threads tid<256 own (batch ub, column jg)
    const int ub = tid >> 6;          // 0..7 (h-owner iff <4)
    const int uj = tid & 63;
    const int jg = j0 + uj;
    float h = 0.f;
    if (ub < 4) {
        h = h0[jg];
        traj[(size_t)(b0 + ub) * (Tn + 1) * Hn + jg] = h;   // t = 0 row
    }

    const int ks   = tid >> 6;        // GEMM k-slice 0..7
    const int kbeg = ks * KSL;

    asm volatile("barrier.cluster.arrive.aligned;" ::: "memory");

    for (int t = 0; t <= Tn; t++) {
        asm volatile("barrier.cluster.wait.aligned;" ::: "memory");
        const int par  = t & 1;
        const float* buf = r4 + par * KP * 4;
        float* bufn = r4 + (1 - par) * KP * 4;

        // store h_t to trajectories (off critical path, overlapped w/ GEMM)
        if (t > 0 && ub < 4)
            traj[(size_t)(b0 + ub) * (Tn + 1) * Hn + (size_t)t * Hn + jg] = h;

        // prefetch noise(t) and x(t+1)
        float nval = 0.f;
        if (t < Tn && ub < 4)
            nval = noise[(size_t)(b0 + ub) * Tn * Hn + (size_t)t * Hn + jg];
        float x0 = 0.f, x1 = 0.f, x2 = 0.f, x3 = 0.f;
        if (t < Tn - 1 && tid < In) {
            const float* xb = input + (size_t)b0 * Tn * In + (size_t)(t + 1) * In + tid;
            const size_t xs = (size_t)Tn * In;
            x0 = xb[0]; x1 = xb[xs]; x2 = xb[2 * xs]; x3 = xb[3 * xs];
        }

        // GEMM slice: y[b][uj] over k in [kbeg, kbeg+KSL)
        if (t < Tn) {
            float a0 = 0.f, a1 = 0.f, a2 = 0.f, a3 = 0.f;
            #pragma unroll 4
            for (int k = kbeg; k < kbeg + KSL; k++) {
                float4 rv = *(const float4*)(buf + k * 4);   // broadcast
                float  w  = Wc[k * JC + uj];
                a0 = fmaf(rv.x, w, a0);
                a1 = fmaf(rv.y, w, a1);
                a2 = fmaf(rv.z, w, a2);
                a3 = fmaf(rv.w, w, a3);
            }
            red[((ks << 2) + 0) * JC + uj] = a0;
            red[((ks << 2) + 1) * JC + uj] = a1;
            red[((ks << 2) + 2) * JC + uj] = a2;
            red[((ks << 2) + 3) * JC + uj] = a3;
        }
        __syncthreads();

        // h update + staging of relu(h_{t+1})
        if (t < Tn && ub < 4) {
            float y = 0.f;
            #pragma unroll
            for (int s = 0; s < NSL; s++)
                y += red[((s << 2) + ub) * JC + uj];
            h = (1.f - ALPHAc) * h + NSTDc * nval + ALPHAc * y;
            stg[uj * 4 + ub] = fmaxf(h, 0.f);
        }

        // out(t-1) partials from buf(t): k in [j0, j0+64), 16x32 split
        if (t > 0) {
            int q = tid & 31, koff = tid >> 5;       // koff 0..15
            int ob = q >> 3, oo = q & 7;
            int kb = j0 + koff * 4;
            float acc = 0.f;
            #pragma unroll
            for (int u = 0; u < 4; u++)
                acc += buf[(kb + u) * 4 + ob] * Wos[(kb + u) * On + oo];
            red2[koff * 32 + q] = acc;
        }
        __syncthreads();

        // DSMEM push: relu(h_{t+1}) slice -> all 8 CTAs' buf(t+1)
        if (t < Tn) {
            int u = tid & 63;            // k-offset within slice
            int r = tid >> 6;            // target rank 0..7
            float4 v = *(float4*)(stg + u * 4);
            float* remote = (float*)cluster.map_shared_rank(
                                (void*)(bufn + (j0 + u) * 4), r);
            *(float4*)remote = v;
            // local x(t+1) rows
            if (tid < In)
                *(float4*)(bufn + (Hn + tid) * 4) = make_float4(x0, x1, x2, x3);
        }

        // out(t-1) final reduce + atomics (overlapped, off critical path)
        if (t > 0 && tid < 32) {
            float s = 0.f;
            #pragma unroll
            for (int w = 0; w < 16; w++) s += red2[w * 32 + tid];
            atomicAdd(&outp[(size_t)(b0 + (tid >> 3)) * Tn * On
                            + (size_t)(t - 1) * On + (tid & 7)], s);
        }

        if (t < Tn)
            asm volatile("barrier.cluster.arrive.aligned;" ::: "memory");
    }
}

extern "C" void kernel_launch(void* const* d_in, const int* in_sizes, int n_in,
                              void* d_out, int out_size)
{
    const float* input = (const float*)d_in[0];
    const float* noise = (const float*)d_in[1];
    const float* wi    = (const float*)d_in[2];
    const float* si    = (const float*)d_in[3];
    const float* wrec  = (const float*)d_in[4];
    const float* bvec  = (const float*)d_in[5];
    const float* wo    = (const float*)d_in[6];
    const float* so    = (const float*)d_in[7];
    const float* wim   = (const float*)d_in[8];
    const float* wrm   = (const float*)d_in[9];
    const float* wom   = (const float*)d_in[10];
    const float* h0    = (const float*)d_in[11];

    float* outp = (float*)d_out;                         // [B, T, O]
    float* traj = (float*)d_out + (size_t)Bn * Tn * On;  // [B, T+1, H]

    const int smem_bytes = SM_TOT * sizeof(float);       // 202752
    cudaFuncSetAttribute(rnn_kernel,
                         cudaFuncAttributeMaxDynamicSharedMemorySize, smem_bytes);

    rnn_kernel<<<GRIDn, NT, smem_bytes>>>(input, noise, wi, si, wrec, bvec,
                                          wo, so, wim, wrm, wom, h0,
                                          outp, traj);
}